// round 12
// baseline (speedup 1.0000x reference)
#include <cuda_runtime.h>

// LearnedPosMapT: out[b,w,m,v,s] = sum_n table[m-n+7, s] * x[b,w,n,v,s] + bias[m]
// Shapes: x (8, 3136, 8, 384) f32, table (15, 8) f32, bias (1, 8, 1) f32.
// W = 8 (window), GAMMA = s = 8, v = 48, DIM = v*s = 384.
//
// Memory-bound (616 MB total). One thread per (window, d/4) float4 column:
// 8 coalesced float4 loads, 64 FMA4, 8 coalesced float4 stores.
// R11 change: weights+bias moved to smem (frees ~68 regs) so occupancy rises
// from 2 to 3 CTAs/SM -> more LDG.128 in flight -> higher DRAM utilization.

#define WINSZ 8
#define DIMSZ 384
#define VEC   (DIMSZ / 4)   // 96 float4 per row
#define ROWF4 VEC           // float4 stride between window rows

__global__ __launch_bounds__(256, 3)
void lpm_kernel(const float* __restrict__ x,
                const float* __restrict__ table,   // (15, 8)
                const float* __restrict__ bias,    // (8)
                float* __restrict__ out,
                int n_win)                          // B * NWIN
{
    // Block-shared weight table: wts[s0/4][k] = table[k][s0 .. s0+3].
    // Only 2 distinct s0 variants (0 and 4) across the whole problem.
    __shared__ float4 wts[2][15];
    __shared__ float  bs[WINSZ];

    const int tid = threadIdx.x;
    if (tid < 30) {
        const int sel = tid / 15;
        const int k   = tid - sel * 15;
        wts[sel][k] = *reinterpret_cast<const float4*>(table + k * 8 + sel * 4);
    }
    if (tid < WINSZ) bs[tid] = bias[tid];
    __syncthreads();

    const int t = blockIdx.x * blockDim.x + tid;
    const int total = n_win * VEC;
    if (t >= total) return;

    const int win = t / VEC;
    const int c   = t - win * VEC;        // float4 column index within a row
    const int sel = c & 1;                // (c*4)&7 ? 1 : 0  -> s0/4

    const float4* __restrict__ xin =
        reinterpret_cast<const float4*>(x) + (size_t)win * (WINSZ * ROWF4) + c;
    float4* __restrict__ o =
        reinterpret_cast<float4*>(out) + (size_t)win * (WINSZ * ROWF4) + c;

    // Front-batched x loads: MLP = 8, each warp-coalesced to a 128B line.
    float4 xv[WINSZ];
#pragma unroll
    for (int n = 0; n < WINSZ; n++)
        xv[n] = xin[n * ROWF4];

#pragma unroll
    for (int m = 0; m < WINSZ; m++) {
        const float bm = bs[m];
        float4 acc = make_float4(bm, bm, bm, bm);
#pragma unroll
        for (int n = 0; n < WINSZ; n++) {
            const float4 w = wts[sel][m - n + 7];  // LDS.128, 2-addr broadcast
            acc.x = fmaf(w.x, xv[n].x, acc.x);
            acc.y = fmaf(w.y, xv[n].y, acc.y);
            acc.z = fmaf(w.z, xv[n].z, acc.z);
            acc.w = fmaf(w.w, xv[n].w, acc.w);
        }
        o[m * ROWF4] = acc;
    }
}

extern "C" void kernel_launch(void* const* d_in, const int* in_sizes, int n_in,
                              void* d_out, int out_size) {
    const float* x     = (const float*)d_in[0];   // (B, NWIN, WIN, DIM)
    const float* table = (const float*)d_in[1];   // (15, 8)
    const float* bias  = (const float*)d_in[2];   // (1, 8, 1)
    float* out = (float*)d_out;

    const int n_win = in_sizes[0] / (WINSZ * DIMSZ);   // B * NWIN = 25088
    const int total_threads = n_win * VEC;             // 2,408,448
    const int block = 256;
    const int grid  = (total_threads + block - 1) / block;

    lpm_kernel<<<grid, block>>>(x, table, bias, out, n_win);
}